// round 15
// baseline (speedup 1.0000x reference)
#include <cuda_runtime.h>
#include <cuda_bf16.h>
#include <math.h>
#include <stdint.h>

// Problem constants
#define B_  4
#define N_  1024
#define C_  1024
#define H_  16
#define HD_ 64
#define M_  (B_ * N_)     // 4096
#define K3_ (3 * C_)      // 3072

// ---------------------------------------------------------------------------
// Scratch (__device__ globals; no allocation allowed)
// ---------------------------------------------------------------------------
__device__ float g_qkv[(size_t)M_ * K3_];            // fp32 q|k|v
__device__ __nv_bfloat16 g_ah[(size_t)M_ * C_];      // activation hi
__device__ __nv_bfloat16 g_al[(size_t)M_ * C_];      // activation lo
__device__ __nv_bfloat16 g_wqh[(size_t)K3_ * C_];    // W_qkv^T hi  [3072,1024]
__device__ __nv_bfloat16 g_wql[(size_t)K3_ * C_];    // W_qkv^T lo
__device__ __nv_bfloat16 g_wph[(size_t)C_ * C_];     // W_proj^T hi [1024,1024]
__device__ __nv_bfloat16 g_wpl[(size_t)C_ * C_];     // W_proj^T lo
// Attention operands, head-major
__device__ __nv_bfloat16 g_qh[(size_t)B_ * H_ * N_ * HD_];
__device__ __nv_bfloat16 g_ql[(size_t)B_ * H_ * N_ * HD_];
__device__ __nv_bfloat16 g_kh[(size_t)B_ * H_ * N_ * HD_];
__device__ __nv_bfloat16 g_kl[(size_t)B_ * H_ * N_ * HD_];
__device__ __nv_bfloat16 g_vth[(size_t)B_ * H_ * HD_ * N_];  // V^T [d][n]
__device__ __nv_bfloat16 g_vtl[(size_t)B_ * H_ * HD_ * N_];

__device__ __forceinline__ uint32_t smem_u32(const void* p) {
    uint32_t a;
    asm("{ .reg .u64 t; cvta.to.shared.u64 t, %1; cvt.u32.u64 %0, t; }"
        : "=r"(a) : "l"(p));
    return a;
}

#define LDSM_X4(r0, r1, r2, r3, addr)                                         \
    asm volatile("ldmatrix.sync.aligned.m8n8.x4.shared.b16 {%0,%1,%2,%3}, [%4];" \
                 : "=r"(r0), "=r"(r1), "=r"(r2), "=r"(r3) : "r"(addr))

#define MMA_BF16(d, a, b)                                                     \
    asm volatile("mma.sync.aligned.m16n8k16.row.col.f32.bf16.bf16.f32 "       \
                 "{%0,%1,%2,%3}, {%4,%5,%6,%7}, {%8,%9}, {%0,%1,%2,%3};"      \
                 : "+f"((d)[0]), "+f"((d)[1]), "+f"((d)[2]), "+f"((d)[3])     \
                 : "r"((a)[0]), "r"((a)[1]), "r"((a)[2]), "r"((a)[3]),        \
                   "r"((b)[0]), "r"((b)[1]))

#define CP_ASYNC16(sa, ga)                                                    \
    asm volatile("cp.async.cg.shared.global [%0], [%1], 16;" :: "r"(sa), "l"(ga))
#define CP_COMMIT() asm volatile("cp.async.commit_group;" ::: "memory")
#define CP_WAIT1()  asm volatile("cp.async.wait_group 1;" ::: "memory")
#define CP_WAIT0()  asm volatile("cp.async.wait_group 0;" ::: "memory")

// SW64 swizzle: conflict-free LDSM on 64-byte rows.
#define SWZ64(x) ((x) ^ (((x) >> 3) & 0x30))

// pack two f32 -> bf16x2 (first arg -> high half, second -> low half)
__device__ __forceinline__ uint32_t pack_bf16(float hi, float lo) {
    uint32_t r;
    asm("cvt.rn.bf16x2.f32 %0, %1, %2;" : "=r"(r) : "f"(hi), "f"(lo));
    return r;
}

// FMA-only exp (no MUFU), deg-5. Logits bounded in [-14,14]; no max shift.
__device__ __forceinline__ float fexp(float x) {
    x = fmaxf(x, -80.0f);
    float y = fmaf(x, 1.4426950408889634f, 12582912.0f);
    int e = (__float_as_int(y) + (127 - 0x4B400000)) << 23;
    float n = y - 12582912.0f;
    float f = fmaf(x, 1.4426950408889634f, -n);
    float p = 1.33335581e-3f;
    p = fmaf(p, f, 9.61812910e-3f);
    p = fmaf(p, f, 5.55041087e-2f);
    p = fmaf(p, f, 2.40226507e-1f);
    p = fmaf(p, f, 6.93147181e-1f);
    p = fmaf(p, f, 1.0f);
    return __int_as_float(e) * p;
}

// ---------------------------------------------------------------------------
// Conversion: split fp32 -> bf16 hi + lo
// ---------------------------------------------------------------------------
__global__ void split_kernel(const float* __restrict__ in,
                             __nv_bfloat16* __restrict__ hi,
                             __nv_bfloat16* __restrict__ lo, int n) {
    int i = (blockIdx.x * blockDim.x + threadIdx.x) * 4;
    if (i >= n) return;
    float4 v = *(const float4*)(in + i);
    float f[4] = {v.x, v.y, v.z, v.w};
    __nv_bfloat16 h[4], l[4];
    #pragma unroll
    for (int j = 0; j < 4; j++) {
        h[j] = __float2bfloat16(f[j]);
        l[j] = __float2bfloat16(f[j] - __bfloat162float(h[j]));
    }
    *(uint2*)(hi + i) = *(uint2*)h;
    *(uint2*)(lo + i) = *(uint2*)l;
}

// ---------------------------------------------------------------------------
// Transpose + split: W[K,Nn] fp32 -> Wt_hi/lo[Nn,K] bf16
// ---------------------------------------------------------------------------
__global__ void transpose_split_kernel(const float* __restrict__ W,
                                       __nv_bfloat16* __restrict__ th,
                                       __nv_bfloat16* __restrict__ tl,
                                       int K, int Nn) {
    __shared__ float tile[32][33];
    int tx = threadIdx.x, ty = threadIdx.y;
    int n0 = blockIdx.x * 32, k0 = blockIdx.y * 32;
    #pragma unroll
    for (int j = 0; j < 4; j++) {
        int k = k0 + ty + j * 8;
        tile[ty + j * 8][tx] = W[(size_t)k * Nn + n0 + tx];
    }
    __syncthreads();
    #pragma unroll
    for (int j = 0; j < 4; j++) {
        int n = n0 + ty + j * 8;
        float v = tile[tx][ty + j * 8];
        __nv_bfloat16 h = __float2bfloat16(v);
        __nv_bfloat16 l = __float2bfloat16(v - __bfloat162float(h));
        th[(size_t)n * K + k0 + tx] = h;
        tl[(size_t)n * K + k0 + tx] = l;
    }
}

// ---------------------------------------------------------------------------
// GEMM via mma.sync bf16 3-split, 2 CTAs/SM, 3-stage cp.async pipeline,
// ONE barrier per K-chunk. Tiles 128x32 bf16, 64B rows, SW64 swizzle.
// (validated R10/R14)
// ---------------------------------------------------------------------------
#define TILEB   8192u                 // 128 rows * 64 B
#define STAGEB  (4u * TILEB)          // Ah | Al | Bh | Bl
#define NSTAGE  3
#define GSMEM   (NSTAGE * STAGEB)     // 98304

__global__ __launch_bounds__(256, 2) void mma_gemm_kernel(
        const __nv_bfloat16* __restrict__ Ah, const __nv_bfloat16* __restrict__ Al,
        const __nv_bfloat16* __restrict__ Bh, const __nv_bfloat16* __restrict__ Bl,
        const float* __restrict__ bias, float* __restrict__ C,
        int M, int Nn, int K) {
    extern __shared__ char smem[];
    const uint32_t sbase = smem_u32(smem);

    const int tid  = threadIdx.x;
    const int lane = tid & 31;
    const int wid  = tid >> 5;
    const int warp_m = (wid & 3) * 32;
    const int warp_n = (wid >> 2) * 64;
    const int row0 = blockIdx.y * 128;
    const int col0 = blockIdx.x * 128;

    const __nv_bfloat16* gbase[4] = {
        Ah + (size_t)row0 * K, Al + (size_t)row0 * K,
        Bh + (size_t)col0 * K, Bl + (size_t)col0 * K
    };

    int c_tile[8], c_r[8];
    uint32_t c_soff[8];
    int c_goff[8];
    #pragma unroll
    for (int i = 0; i < 8; i++) {
        int u = tid + i * 256;
        int tile = u >> 9;
        int r    = (u >> 2) & 127;
        int c16  = u & 3;
        c_tile[i] = tile;
        c_r[i]    = r;
        uint32_t logical = (uint32_t)(r * 64 + c16 * 16);
        c_soff[i] = tile * TILEB + SWZ64(logical);
        c_goff[i] = c16 * 8;
    }

    const int NCH = K >> 5;

#define G_ISSUE(chunk) do {                                                   \
        const int k0_ = (chunk) * 32;                                         \
        const uint32_t sb_ = sbase + ((chunk) % NSTAGE) * STAGEB;             \
        _Pragma("unroll")                                                     \
        for (int i = 0; i < 8; i++) {                                         \
            const __nv_bfloat16* g =                                          \
                gbase[c_tile[i]] + (size_t)c_r[i] * K + k0_ + c_goff[i];      \
            CP_ASYNC16(sb_ + c_soff[i], g);                                   \
        }                                                                     \
        CP_COMMIT();                                                          \
    } while (0)

    G_ISSUE(0);
    G_ISSUE(1);

    float acc[2][8][4];
    #pragma unroll
    for (int ma = 0; ma < 2; ma++)
        #pragma unroll
        for (int na = 0; na < 8; na++)
            #pragma unroll
            for (int q = 0; q < 4; q++) acc[ma][na][q] = 0.0f;

    const int arow  = warp_m + (lane & 15);
    const int akoff = (lane >> 4) * 8;
    const int brow  = warp_n + ((lane >> 4) & 1) * 8 + (lane & 7);
    const int bkoff = ((lane >> 3) & 1) * 8;

    for (int c = 0; c < NCH; c++) {
        if (c + 1 < NCH) CP_WAIT1(); else CP_WAIT0();
        __syncthreads();
        if (c + 2 < NCH) G_ISSUE(c + 2);

        const uint32_t st = sbase + (c % NSTAGE) * STAGEB;
        #pragma unroll
        for (int ks = 0; ks < 2; ks++) {
            const uint32_t kb = (uint32_t)(ks * 32);
            uint32_t ahf[2][4], alf[2][4];
            uint32_t bfr[8][2];

            #pragma unroll
            for (int ma = 0; ma < 2; ma++) {
                uint32_t lg = (uint32_t)((arow + ma * 16) * 64) + kb + akoff * 2;
                LDSM_X4(ahf[ma][0], ahf[ma][1], ahf[ma][2], ahf[ma][3],
                        st + SWZ64(lg));
            }
            #pragma unroll
            for (int j = 0; j < 4; j++) {
                uint32_t lg = (uint32_t)((brow + j * 16) * 64) + kb + bkoff * 2;
                LDSM_X4(bfr[2 * j][0], bfr[2 * j][1],
                        bfr[2 * j + 1][0], bfr[2 * j + 1][1],
                        st + 2u * TILEB + SWZ64(lg));
            }
            #pragma unroll
            for (int ma = 0; ma < 2; ma++) {
                uint32_t lg = (uint32_t)((arow + ma * 16) * 64) + kb + akoff * 2;
                LDSM_X4(alf[ma][0], alf[ma][1], alf[ma][2], alf[ma][3],
                        st + TILEB + SWZ64(lg));
            }

            // pass0: Ah * Bh
            #pragma unroll
            for (int ma = 0; ma < 2; ma++)
                #pragma unroll
                for (int na = 0; na < 8; na++)
                    MMA_BF16(acc[ma][na], ahf[ma], bfr[na]);
            // pass2: Al * Bh (Bh dead after)
            #pragma unroll
            for (int ma = 0; ma < 2; ma++)
                #pragma unroll
                for (int na = 0; na < 8; na++)
                    MMA_BF16(acc[ma][na], alf[ma], bfr[na]);

            #pragma unroll
            for (int j = 0; j < 4; j++) {
                uint32_t lg = (uint32_t)((brow + j * 16) * 64) + kb + bkoff * 2;
                LDSM_X4(bfr[2 * j][0], bfr[2 * j][1],
                        bfr[2 * j + 1][0], bfr[2 * j + 1][1],
                        st + 3u * TILEB + SWZ64(lg));
            }
            // pass1: Ah * Bl
            #pragma unroll
            for (int ma = 0; ma < 2; ma++)
                #pragma unroll
                for (int na = 0; na < 8; na++)
                    MMA_BF16(acc[ma][na], ahf[ma], bfr[na]);
        }
    }
#undef G_ISSUE

    #pragma unroll
    for (int na = 0; na < 8; na++) {
        const int cc = col0 + warp_n + na * 8 + (lane & 3) * 2;
        float2 bb = *(const float2*)(bias + cc);
        #pragma unroll
        for (int ma = 0; ma < 2; ma++) {
            const int r0r = row0 + warp_m + ma * 16 + (lane >> 2);
            float2 v0 = {acc[ma][na][0] + bb.x, acc[ma][na][1] + bb.y};
            float2 v1 = {acc[ma][na][2] + bb.x, acc[ma][na][3] + bb.y};
            *(float2*)(C + (size_t)r0r * Nn + cc) = v0;
            *(float2*)(C + (size_t)(r0r + 8) * Nn + cc) = v1;
        }
    }
}

// ---------------------------------------------------------------------------
// RMSNorm q,k + split to bf16 hi/lo, head-major [B,H,N,64].
// ---------------------------------------------------------------------------
__global__ void rmsnorm_split_kernel(const float* __restrict__ q_scale,
                                     const float* __restrict__ k_scale) {
    const int rr = blockIdx.x;
    const int h  = blockIdx.y * 4 + threadIdx.y;
    const int t  = threadIdx.x;
    const int b  = rr >> 10, n = rr & 1023;
    const float* in = g_qkv + (size_t)rr * K3_ + h * HD_;
    const size_t ob = ((size_t)(b * H_ + h) * N_ + n) * HD_;

    #pragma unroll
    for (int part = 0; part < 2; part++) {
        const float* ip = in + part * C_;
        float v0 = ip[t], v1 = ip[t + 32];
        float ss = v0 * v0 + v1 * v1;
        #pragma unroll
        for (int off = 16; off >= 1; off >>= 1)
            ss += __shfl_xor_sync(0xffffffffu, ss, off);
        float inv = 1.0f / (sqrtf(ss * (1.0f / 64.0f)) + 1e-8f);
        const float* sc = part ? k_scale : q_scale;
        float w0 = sc[t] * v0 * inv;
        float w1 = sc[t + 32] * v1 * inv;
        __nv_bfloat16 h0 = __float2bfloat16(w0);
        __nv_bfloat16 l0 = __float2bfloat16(w0 - __bfloat162float(h0));
        __nv_bfloat16 h1 = __float2bfloat16(w1);
        __nv_bfloat16 l1 = __float2bfloat16(w1 - __bfloat162float(h1));
        if (part == 0) {
            g_qh[ob + t] = h0;  g_ql[ob + t] = l0;
            g_qh[ob + t + 32] = h1;  g_ql[ob + t + 32] = l1;
        } else {
            g_kh[ob + t] = h0;  g_kl[ob + t] = l0;
            g_kh[ob + t + 32] = h1;  g_kl[ob + t + 32] = l1;
        }
    }
}

// ---------------------------------------------------------------------------
// V transpose + split: per head V[n][d] -> Vt[d][n] bf16 hi/lo.
// ---------------------------------------------------------------------------
__global__ void vt_split_kernel() {
    __shared__ float tile[32][33];
    const int tx = threadIdx.x, ty = threadIdx.y;
    const int n0 = blockIdx.x * 32;
    const int h  = blockIdx.y >> 1;
    const int d0 = (blockIdx.y & 1) * 32;
    const int b  = blockIdx.z;
    #pragma unroll
    for (int j = 0; j < 4; j++) {
        int n = n0 + ty + j * 8;
        tile[ty + j * 8][tx] =
            g_qkv[(size_t)(b * N_ + n) * K3_ + 2 * C_ + h * HD_ + d0 + tx];
    }
    __syncthreads();
    #pragma unroll
    for (int j = 0; j < 4; j++) {
        int d = d0 + ty + j * 8;
        float v = tile[tx][ty + j * 8];
        __nv_bfloat16 hh = __float2bfloat16(v);
        __nv_bfloat16 ll = __float2bfloat16(v - __bfloat162float(hh));
        size_t oi = ((size_t)(b * H_ + h) * HD_ + d) * N_ + n0 + tx;
        g_vth[oi] = hh;
        g_vtl[oi] = ll;
    }
}

// ---------------------------------------------------------------------------
// Tensor-core flash attention: pipelined loads, bias double-buffered in smem,
// no-max softmax, softmax(half1) interleaved with PV(half0) so FMA-pipe work
// hides under tensor-pipe work.
// ---------------------------------------------------------------------------
#define QKPITCH  72
#define QKTILE   (128 * QKPITCH * 2)   // 18432
#define KH_OFF   0u
#define KL_OFF   18432u
#define VH_OFF   36864u
#define VL_OFF   54272u
#define BIA_OFF  71680u
#define BIASZ    67584u
#define VPITCH   136
#define ATT_SMEM 206848

__global__ __launch_bounds__(256, 1) void mma_attn_kernel(
        const float* __restrict__ bias) {
    extern __shared__ char smem[];
    const uint32_t sb = smem_u32(smem);
    const int tid = threadIdx.x;
    const int lane = tid & 31;
    const int w = tid >> 5;
    const int q0 = blockIdx.x * 128;
    const int h  = blockIdx.y;
    const int b  = blockIdx.z;

    const size_t headNK = ((size_t)(b * H_ + h)) * N_ * HD_;
    const __nv_bfloat16* qh = g_qh + headNK + (size_t)q0 * HD_;
    const __nv_bfloat16* ql = g_ql + headNK + (size_t)q0 * HD_;
    const __nv_bfloat16* kh = g_kh + headNK;
    const __nv_bfloat16* kl = g_kl + headNK;
    const __nv_bfloat16* vth = g_vth + headNK;
    const __nv_bfloat16* vtl = g_vtl + headNK;
    const float* bptr = bias + (((size_t)(b * H_ + h)) * N_ + q0) * N_;

    // ---- Stage Q into bias buf 0, load fragments to registers ----
    #pragma unroll
    for (int i = 0; i < 8; i++) {
        int u = tid + i * 256;
        int mat = u >> 10, r = (u >> 3) & 127, ch = u & 7;
        uint32_t sa = sb + BIA_OFF + mat * QKTILE + (r * QKPITCH + ch * 8) * 2;
        const __nv_bfloat16* g = (mat ? ql : qh) + (size_t)r * HD_ + ch * 8;
        CP_ASYNC16(sa, g);
    }
    CP_COMMIT(); CP_WAIT0();
    __syncthreads();

    uint32_t qfh[4][4], qfl[4][4];
    {
        const int arow = w * 16 + (lane & 15);
        const int ak = (lane >> 4) * 8;
        #pragma unroll
        for (int ks = 0; ks < 4; ks++) {
            uint32_t ad = sb + BIA_OFF + (arow * QKPITCH + ks * 16 + ak) * 2;
            LDSM_X4(qfh[ks][0], qfh[ks][1], qfh[ks][2], qfh[ks][3], ad);
            LDSM_X4(qfl[ks][0], qfl[ks][1], qfl[ks][2], qfl[ks][3], ad + QKTILE);
        }
    }
    __syncthreads();

#define ISSUE_KB(kt_) do {                                                    \
        const int k0_ = (kt_) * 128;                                          \
        _Pragma("unroll")                                                     \
        for (int i = 0; i < 8; i++) {                                         \
            int u = tid + i * 256;                                            \
            int mat = u >> 10, r = (u >> 3) & 127, ch = u & 7;                \
            uint32_t sa = sb + mat * (uint32_t)QKTILE + (r * QKPITCH + ch * 8) * 2; \
            const __nv_bfloat16* g = (mat ? kl : kh) + (size_t)(k0_ + r) * HD_ + ch * 8; \
            CP_ASYNC16(sa, g);                                                \
        }                                                                     \
        const uint32_t bb_ = sb + BIA_OFF + ((kt_) & 1) * BIASZ;              \
        _Pragma("unroll")                                                     \
        for (int i = 0; i < 16; i++) {                                        \
            int u = tid + i * 256;                                            \
            int r = u >> 5, ch = u & 31;                                      \
            CP_ASYNC16(bb_ + r * 528u + ch * 16,                              \
                       bptr + (size_t)r * N_ + k0_ + ch * 4);                 \
        }                                                                     \
        CP_COMMIT();                                                          \
    } while (0)

#define ISSUE_V(kt_) do {                                                     \
        const int k0_ = (kt_) * 128;                                          \
        _Pragma("unroll")                                                     \
        for (int i = 0; i < 8; i++) {                                         \
            int u = tid + i * 256;                                            \
            int mat = u >> 10, d = (u >> 4) & 63, ch = u & 15;                \
            uint32_t sa = sb + VH_OFF + mat * 17408u + (d * VPITCH + ch * 8) * 2; \
            const __nv_bfloat16* g = (mat ? vtl : vth) + (size_t)d * N_ + k0_ + ch * 8; \
            CP_ASYNC16(sa, g);                                                \
        }                                                                     \
        CP_COMMIT();                                                          \
    } while (0)

// Pack one ko (two j's) of softmax numerators into pah/pal[ko].
#define PACK_KO(ko_) do {                                                     \
        float p[8];                                                           \
        _Pragma("unroll")                                                     \
        for (int half = 0; half < 2; half++) {                                \
            const int j = 2 * (ko_) + half;                                   \
            p[half * 4 + 0] = fexp(sacc[j][0]);                               \
            p[half * 4 + 1] = fexp(sacc[j][1]);                               \
            p[half * 4 + 2] = fexp(sacc[j][2]);                               \
            p[half * 4 + 3] = fexp(sacc[j][3]);                               \
            rs0 += p[half * 4 + 0] + p[half * 4 + 1];                         \
            rs1 += p[half * 4 + 2] + p[half * 4 + 3];                         \
        }                                                                     \
        _Pragma("unroll")                                                     \
        for (int half = 0; half < 2; half++) {                                \
            uint32_t hi01 = pack_bf16(p[half * 4 + 1], p[half * 4 + 0]);      \
            uint32_t hi23 = pack_bf16(p[half * 4 + 3], p[half * 4 + 2]);      \
            float h0 = __int_as_float(hi01 << 16);                            \
            float h1 = __int_as_float(hi01 & 0xffff0000u);                    \
            float h2 = __int_as_float(hi23 << 16);                            \
            float h3 = __int_as_float(hi23 & 0xffff0000u);                    \
            pah[ko_][half * 2 + 0] = hi01;                                    \
            pah[ko_][half * 2 + 1] = hi23;                                    \
            pal[ko_][half * 2 + 0] =                                          \
                pack_bf16(p[half * 4 + 1] - h1, p[half * 4 + 0] - h0);        \
            pal[ko_][half * 2 + 1] =                                          \
                pack_bf16(p[half * 4 + 3] - h3, p[half * 4 + 2] - h2);        \
        }                                                                     \
    } while (0)

// PV MMAs for one ko.
#define PV_KO(ko_) do {                                                       \
        uint32_t vb[8][2];                                                    \
        _Pragma("unroll")                                                     \
        for (int d2 = 0; d2 < 4; d2++) {                                      \
            uint32_t vd = sb + VH_OFF +                                       \
                ((d2 * 16 + brow_k) * VPITCH + (ko_) * 16 + bkoff) * 2;       \
            LDSM_X4(vb[2 * d2][0], vb[2 * d2][1],                             \
                    vb[2 * d2 + 1][0], vb[2 * d2 + 1][1], vd);                \
        }                                                                     \
        _Pragma("unroll")                                                     \
        for (int dj = 0; dj < 8; dj++) MMA_BF16(oacc[dj], pah[ko_], vb[dj]);  \
        _Pragma("unroll")                                                     \
        for (int dj = 0; dj < 8; dj++) MMA_BF16(oacc[dj], pal[ko_], vb[dj]);  \
        _Pragma("unroll")                                                     \
        for (int d2 = 0; d2 < 4; d2++) {                                      \
            uint32_t vd = sb + VL_OFF +                                       \
                ((d2 * 16 + brow_k) * VPITCH + (ko_) * 16 + bkoff) * 2;       \
            LDSM_X4(vb[2 * d2][0], vb[2 * d2][1],                             \
                    vb[2 * d2 + 1][0], vb[2 * d2 + 1][1], vd);                \
        }                                                                     \
        _Pragma("unroll")                                                     \
        for (int dj = 0; dj < 8; dj++) MMA_BF16(oacc[dj], pah[ko_], vb[dj]);  \
    } while (0)

    ISSUE_KB(0);
    ISSUE_V(0);

    float oacc[8][4];
    #pragma unroll
    for (int dj = 0; dj < 8; dj++)
        #pragma unroll
        for (int q = 0; q < 4; q++) oacc[dj][q] = 0.0f;
    float l0 = 0.0f, l1 = 0.0f;

    const int brow_k = ((lane >> 4) & 1) * 8 + (lane & 7);
    const int bkoff  = ((lane >> 3) & 1) * 8;
    const int r0 = w * 16 + (lane >> 2);
    const int cc2 = (lane & 3) * 2;

    for (int kt = 0; kt < 8; kt++) {
        CP_WAIT1();
        __syncthreads();

        float sacc[16][4];
        #pragma unroll
        for (int j = 0; j < 16; j++)
            #pragma unroll
            for (int q = 0; q < 4; q++) sacc[j][q] = 0.0f;

        #pragma unroll
        for (int ks = 0; ks < 4; ks++) {
            uint32_t bf[16][2];
            #pragma unroll
            for (int j2 = 0; j2 < 8; j2++) {
                uint32_t bd = sb + KH_OFF +
                    ((j2 * 16 + brow_k) * QKPITCH + ks * 16 + bkoff) * 2;
                LDSM_X4(bf[2 * j2][0], bf[2 * j2][1],
                        bf[2 * j2 + 1][0], bf[2 * j2 + 1][1], bd);
            }
            #pragma unroll
            for (int j = 0; j < 16; j++) MMA_BF16(sacc[j], qfh[ks], bf[j]);
            #pragma unroll
            for (int j = 0; j < 16; j++) MMA_BF16(sacc[j], qfl[ks], bf[j]);
        }
        #pragma unroll
        for (int ks = 0; ks < 4; ks++) {
            uint32_t bf[16][2];
            #pragma unroll
            for (int j2 = 0; j2 < 8; j2++) {
                uint32_t bd = sb + KL_OFF +
                    ((j2 * 16 + brow_k) * QKPITCH + ks * 16 + bkoff) * 2;
                LDSM_X4(bf[2 * j2][0], bf[2 * j2][1],
                        bf[2 * j2 + 1][0], bf[2 * j2 + 1][1], bd);
            }
            #pragma unroll
            for (int j = 0; j < 16; j++) MMA_BF16(sacc[j], qfh[ks], bf[j]);
        }

        __syncthreads();
        if (kt + 1 < 8) ISSUE_KB(kt + 1);

        // ---- bias add (all 16 j), no max shift ----
        const char* bcur = smem + BIA_OFF + (kt & 1) * BIASZ;
        #pragma unroll
        for (int j = 0; j < 16; j++) {
            const int col = j * 8 + cc2;
            float2 b0 = *(const float2*)(bcur + r0 * 528 + col * 4);
            float2 b1 = *(const float2*)(bcur + (r0 + 8) * 528 + col * 4);
            sacc[j][0] = fmaf(sacc[j][0], 0.125f, b0.x);
            sacc[j][1] = fmaf(sacc[j][1], 0.125f, b0.y);
            sacc[j][2] = fmaf(sacc[j][2], 0.125f, b1.x);
            sacc[j][3] = fmaf(sacc[j][3], 0.125f, b1.y);
        }

        float rs0 = 0.0f, rs1 = 0.0f;
        uint32_t pah[8][4], pal[8][4];

        // pack half0: ko 0..3
        #pragma unroll
        for (int ko = 0; ko < 4; ko++) PACK_KO(ko);

        // V_cur ready (KB_next may still be in flight)
        CP_WAIT1();

        // interleave: pack(ko+4) [FMA pipe] with PV(ko) [tensor pipe]
        #pragma unroll
        for (int ko = 0; ko < 4; ko++) {
            PACK_KO(ko + 4);
            PV_KO(ko);
        }
        // drain PV half1
        #pragma unroll
        for (int ko = 4; ko < 8; ko++) PV_KO(ko);

        rs0 += __shfl_xor_sync(0xffffffffu, rs0, 1);
        rs0 += __shfl_xor_sync(0xffffffffu, rs0, 2);
        rs1 += __shfl_xor_sync(0xffffffffu, rs1, 1);
        rs1 += __shfl_xor_sync(0xffffffffu, rs1, 2);
        l0 += rs0;
        l1 += rs1;

        __syncthreads();
        if (kt + 1 < 8) ISSUE_V(kt + 1);
    }

    const float il0 = 1.0f / l0, il1 = 1.0f / l1;
    #pragma unroll
    for (int dj = 0; dj < 8; dj++) {
        const int col = h * HD_ + dj * 8 + cc2;
        const size_t ra = (size_t)(b * N_ + q0 + r0) * C_ + col;
        const size_t rb = (size_t)(b * N_ + q0 + r0 + 8) * C_ + col;
        float v0 = oacc[dj][0] * il0, v1 = oacc[dj][1] * il0;
        float v2 = oacc[dj][2] * il1, v3 = oacc[dj][3] * il1;

        uint32_t h01 = pack_bf16(v1, v0);
        uint32_t h23 = pack_bf16(v3, v2);
        float f0 = __int_as_float(h01 << 16);
        float f1 = __int_as_float(h01 & 0xffff0000u);
        float f2 = __int_as_float(h23 << 16);
        float f3 = __int_as_float(h23 & 0xffff0000u);
        uint32_t l01 = pack_bf16(v1 - f1, v0 - f0);
        uint32_t l23 = pack_bf16(v3 - f3, v2 - f2);

        *(uint32_t*)(g_ah + ra) = h01;
        *(uint32_t*)(g_al + ra) = l01;
        *(uint32_t*)(g_ah + rb) = h23;
        *(uint32_t*)(g_al + rb) = l23;
    }
#undef ISSUE_KB
#undef ISSUE_V
#undef PACK_KO
#undef PV_KO
}

// ---------------------------------------------------------------------------
// Launch
// ---------------------------------------------------------------------------
extern "C" void kernel_launch(void* const* d_in, const int* in_sizes, int n_in,
                              void* d_out, int out_size) {
    const float* x       = (const float*)d_in[0];
    const float* bias    = (const float*)d_in[1];
    const float* W_qkv   = (const float*)d_in[2];
    const float* b_qkv   = (const float*)d_in[3];
    const float* q_scale = (const float*)d_in[4];
    const float* k_scale = (const float*)d_in[5];
    const float* W_proj  = (const float*)d_in[6];
    const float* b_proj  = (const float*)d_in[7];
    float* out = (float*)d_out;

    float* qkv;
    __nv_bfloat16 *ah, *al, *wqh, *wql, *wph, *wpl;
    cudaGetSymbolAddress((void**)&qkv, g_qkv);
    cudaGetSymbolAddress((void**)&ah, g_ah);
    cudaGetSymbolAddress((void**)&al, g_al);
    cudaGetSymbolAddress((void**)&wqh, g_wqh);
    cudaGetSymbolAddress((void**)&wql, g_wql);
    cudaGetSymbolAddress((void**)&wph, g_wph);
    cudaGetSymbolAddress((void**)&wpl, g_wpl);

    cudaFuncSetAttribute(mma_gemm_kernel,
                         cudaFuncAttributeMaxDynamicSharedMemorySize, GSMEM);
    cudaFuncSetAttribute(mma_attn_kernel,
                         cudaFuncAttributeMaxDynamicSharedMemorySize, ATT_SMEM);

    // 0) Conversions
    split_kernel<<<(M_ * C_ / 4 + 255) / 256, 256>>>(x, ah, al, M_ * C_);
    transpose_split_kernel<<<dim3(K3_ / 32, C_ / 32), dim3(32, 8)>>>(W_qkv, wqh, wql, C_, K3_);
    transpose_split_kernel<<<dim3(C_ / 32, C_ / 32), dim3(32, 8)>>>(W_proj, wph, wpl, C_, C_);

    // 1) QKV GEMM
    mma_gemm_kernel<<<dim3(K3_ / 128, M_ / 128), 256, GSMEM>>>(
        ah, al, wqh, wql, b_qkv, qkv, M_, K3_, C_);

    // 2) RMSNorm + split q,k; transpose + split v
    rmsnorm_split_kernel<<<dim3(M_, 4), dim3(32, 4)>>>(q_scale, k_scale);
    vt_split_kernel<<<dim3(32, 32, 4), dim3(32, 8)>>>();

    // 3) Tensor-core flash attention (writes bf16 hi/lo directly)
    mma_attn_kernel<<<dim3(8, 16, 4), 256, ATT_SMEM>>>(bias);

    // 4) Proj GEMM (reads attention output hi/lo)
    mma_gemm_kernel<<<dim3(C_ / 128, M_ / 128), 256, GSMEM>>>(
        ah, al, wph, wpl, b_proj, out, M_, C_, C_);
}

// round 16
// speedup vs baseline: 1.0487x; 1.0487x over previous
#include <cuda_runtime.h>
#include <cuda_bf16.h>
#include <math.h>
#include <stdint.h>

// Problem constants
#define B_  4
#define N_  1024
#define C_  1024
#define H_  16
#define HD_ 64
#define M_  (B_ * N_)     // 4096
#define K3_ (3 * C_)      // 3072

// ---------------------------------------------------------------------------
// Scratch (__device__ globals; no allocation allowed)
// ---------------------------------------------------------------------------
__device__ float g_qkv[(size_t)M_ * K3_];            // fp32 q|k|v
__device__ __nv_bfloat16 g_ah[(size_t)M_ * C_];      // activation hi
__device__ __nv_bfloat16 g_al[(size_t)M_ * C_];      // activation lo
__device__ __nv_bfloat16 g_wqh[(size_t)K3_ * C_];    // W_qkv^T hi  [3072,1024]
__device__ __nv_bfloat16 g_wql[(size_t)K3_ * C_];    // W_qkv^T lo
__device__ __nv_bfloat16 g_wph[(size_t)C_ * C_];     // W_proj^T hi [1024,1024]
__device__ __nv_bfloat16 g_wpl[(size_t)C_ * C_];     // W_proj^T lo
// Attention operands, head-major
__device__ __nv_bfloat16 g_qh[(size_t)B_ * H_ * N_ * HD_];
__device__ __nv_bfloat16 g_ql[(size_t)B_ * H_ * N_ * HD_];
__device__ __nv_bfloat16 g_kh[(size_t)B_ * H_ * N_ * HD_];
__device__ __nv_bfloat16 g_kl[(size_t)B_ * H_ * N_ * HD_];
__device__ __nv_bfloat16 g_vth[(size_t)B_ * H_ * HD_ * N_];  // V^T [d][n]
__device__ __nv_bfloat16 g_vtl[(size_t)B_ * H_ * HD_ * N_];

__device__ __forceinline__ uint32_t smem_u32(const void* p) {
    uint32_t a;
    asm("{ .reg .u64 t; cvta.to.shared.u64 t, %1; cvt.u32.u64 %0, t; }"
        : "=r"(a) : "l"(p));
    return a;
}

#define LDSM_X4(r0, r1, r2, r3, addr)                                         \
    asm volatile("ldmatrix.sync.aligned.m8n8.x4.shared.b16 {%0,%1,%2,%3}, [%4];" \
                 : "=r"(r0), "=r"(r1), "=r"(r2), "=r"(r3) : "r"(addr))

#define MMA_BF16(d, a, b)                                                     \
    asm volatile("mma.sync.aligned.m16n8k16.row.col.f32.bf16.bf16.f32 "       \
                 "{%0,%1,%2,%3}, {%4,%5,%6,%7}, {%8,%9}, {%0,%1,%2,%3};"      \
                 : "+f"((d)[0]), "+f"((d)[1]), "+f"((d)[2]), "+f"((d)[3])     \
                 : "r"((a)[0]), "r"((a)[1]), "r"((a)[2]), "r"((a)[3]),        \
                   "r"((b)[0]), "r"((b)[1]))

#define CP_ASYNC16(sa, ga)                                                    \
    asm volatile("cp.async.cg.shared.global [%0], [%1], 16;" :: "r"(sa), "l"(ga))
#define CP_COMMIT() asm volatile("cp.async.commit_group;" ::: "memory")
#define CP_WAIT1()  asm volatile("cp.async.wait_group 1;" ::: "memory")
#define CP_WAIT0()  asm volatile("cp.async.wait_group 0;" ::: "memory")

// SW64 swizzle: conflict-free LDSM on 64-byte rows.
#define SWZ64(x) ((x) ^ (((x) >> 3) & 0x30))

// pack two f32 -> bf16x2 (first arg -> high half, second -> low half)
__device__ __forceinline__ uint32_t pack_bf16(float hi, float lo) {
    uint32_t r;
    asm("cvt.rn.bf16x2.f32 %0, %1, %2;" : "=r"(r) : "f"(hi), "f"(lo));
    return r;
}

// FMA-only exp (no MUFU), deg-5. Logits bounded in [-14,14]; no max shift.
__device__ __forceinline__ float fexp(float x) {
    x = fmaxf(x, -80.0f);
    float y = fmaf(x, 1.4426950408889634f, 12582912.0f);
    int e = (__float_as_int(y) + (127 - 0x4B400000)) << 23;
    float n = y - 12582912.0f;
    float f = fmaf(x, 1.4426950408889634f, -n);
    float p = 1.33335581e-3f;
    p = fmaf(p, f, 9.61812910e-3f);
    p = fmaf(p, f, 5.55041087e-2f);
    p = fmaf(p, f, 2.40226507e-1f);
    p = fmaf(p, f, 6.93147181e-1f);
    p = fmaf(p, f, 1.0f);
    return __int_as_float(e) * p;
}

// ---------------------------------------------------------------------------
// Conversion: split fp32 -> bf16 hi + lo
// ---------------------------------------------------------------------------
__global__ void split_kernel(const float* __restrict__ in,
                             __nv_bfloat16* __restrict__ hi,
                             __nv_bfloat16* __restrict__ lo, int n) {
    int i = (blockIdx.x * blockDim.x + threadIdx.x) * 4;
    if (i >= n) return;
    float4 v = *(const float4*)(in + i);
    float f[4] = {v.x, v.y, v.z, v.w};
    __nv_bfloat16 h[4], l[4];
    #pragma unroll
    for (int j = 0; j < 4; j++) {
        h[j] = __float2bfloat16(f[j]);
        l[j] = __float2bfloat16(f[j] - __bfloat162float(h[j]));
    }
    *(uint2*)(hi + i) = *(uint2*)h;
    *(uint2*)(lo + i) = *(uint2*)l;
}

// ---------------------------------------------------------------------------
// Transpose + split: W[K,Nn] fp32 -> Wt_hi/lo[Nn,K] bf16
// ---------------------------------------------------------------------------
__global__ void transpose_split_kernel(const float* __restrict__ W,
                                       __nv_bfloat16* __restrict__ th,
                                       __nv_bfloat16* __restrict__ tl,
                                       int K, int Nn) {
    __shared__ float tile[32][33];
    int tx = threadIdx.x, ty = threadIdx.y;
    int n0 = blockIdx.x * 32, k0 = blockIdx.y * 32;
    #pragma unroll
    for (int j = 0; j < 4; j++) {
        int k = k0 + ty + j * 8;
        tile[ty + j * 8][tx] = W[(size_t)k * Nn + n0 + tx];
    }
    __syncthreads();
    #pragma unroll
    for (int j = 0; j < 4; j++) {
        int n = n0 + ty + j * 8;
        float v = tile[tx][ty + j * 8];
        __nv_bfloat16 h = __float2bfloat16(v);
        __nv_bfloat16 l = __float2bfloat16(v - __bfloat162float(h));
        th[(size_t)n * K + k0 + tx] = h;
        tl[(size_t)n * K + k0 + tx] = l;
    }
}

// ---------------------------------------------------------------------------
// GEMM via mma.sync bf16 3-split, 2 CTAs/SM, 3-stage cp.async pipeline,
// ONE barrier per K-chunk. Tiles 128x32 bf16, 64B rows, SW64 swizzle.
// (validated R10/R14)
// ---------------------------------------------------------------------------
#define TILEB   8192u                 // 128 rows * 64 B
#define STAGEB  (4u * TILEB)          // Ah | Al | Bh | Bl
#define NSTAGE  3
#define GSMEM   (NSTAGE * STAGEB)     // 98304

__global__ __launch_bounds__(256, 2) void mma_gemm_kernel(
        const __nv_bfloat16* __restrict__ Ah, const __nv_bfloat16* __restrict__ Al,
        const __nv_bfloat16* __restrict__ Bh, const __nv_bfloat16* __restrict__ Bl,
        const float* __restrict__ bias, float* __restrict__ C,
        int M, int Nn, int K) {
    extern __shared__ char smem[];
    const uint32_t sbase = smem_u32(smem);

    const int tid  = threadIdx.x;
    const int lane = tid & 31;
    const int wid  = tid >> 5;
    const int warp_m = (wid & 3) * 32;
    const int warp_n = (wid >> 2) * 64;
    const int row0 = blockIdx.y * 128;
    const int col0 = blockIdx.x * 128;

    const __nv_bfloat16* gbase[4] = {
        Ah + (size_t)row0 * K, Al + (size_t)row0 * K,
        Bh + (size_t)col0 * K, Bl + (size_t)col0 * K
    };

    int c_tile[8], c_r[8];
    uint32_t c_soff[8];
    int c_goff[8];
    #pragma unroll
    for (int i = 0; i < 8; i++) {
        int u = tid + i * 256;
        int tile = u >> 9;
        int r    = (u >> 2) & 127;
        int c16  = u & 3;
        c_tile[i] = tile;
        c_r[i]    = r;
        uint32_t logical = (uint32_t)(r * 64 + c16 * 16);
        c_soff[i] = tile * TILEB + SWZ64(logical);
        c_goff[i] = c16 * 8;
    }

    const int NCH = K >> 5;

#define G_ISSUE(chunk) do {                                                   \
        const int k0_ = (chunk) * 32;                                         \
        const uint32_t sb_ = sbase + ((chunk) % NSTAGE) * STAGEB;             \
        _Pragma("unroll")                                                     \
        for (int i = 0; i < 8; i++) {                                         \
            const __nv_bfloat16* g =                                          \
                gbase[c_tile[i]] + (size_t)c_r[i] * K + k0_ + c_goff[i];      \
            CP_ASYNC16(sb_ + c_soff[i], g);                                   \
        }                                                                     \
        CP_COMMIT();                                                          \
    } while (0)

    G_ISSUE(0);
    G_ISSUE(1);

    float acc[2][8][4];
    #pragma unroll
    for (int ma = 0; ma < 2; ma++)
        #pragma unroll
        for (int na = 0; na < 8; na++)
            #pragma unroll
            for (int q = 0; q < 4; q++) acc[ma][na][q] = 0.0f;

    const int arow  = warp_m + (lane & 15);
    const int akoff = (lane >> 4) * 8;
    const int brow  = warp_n + ((lane >> 4) & 1) * 8 + (lane & 7);
    const int bkoff = ((lane >> 3) & 1) * 8;

    for (int c = 0; c < NCH; c++) {
        if (c + 1 < NCH) CP_WAIT1(); else CP_WAIT0();
        __syncthreads();
        if (c + 2 < NCH) G_ISSUE(c + 2);

        const uint32_t st = sbase + (c % NSTAGE) * STAGEB;
        #pragma unroll
        for (int ks = 0; ks < 2; ks++) {
            const uint32_t kb = (uint32_t)(ks * 32);
            uint32_t ahf[2][4], alf[2][4];
            uint32_t bfr[8][2];

            #pragma unroll
            for (int ma = 0; ma < 2; ma++) {
                uint32_t lg = (uint32_t)((arow + ma * 16) * 64) + kb + akoff * 2;
                LDSM_X4(ahf[ma][0], ahf[ma][1], ahf[ma][2], ahf[ma][3],
                        st + SWZ64(lg));
            }
            #pragma unroll
            for (int j = 0; j < 4; j++) {
                uint32_t lg = (uint32_t)((brow + j * 16) * 64) + kb + bkoff * 2;
                LDSM_X4(bfr[2 * j][0], bfr[2 * j][1],
                        bfr[2 * j + 1][0], bfr[2 * j + 1][1],
                        st + 2u * TILEB + SWZ64(lg));
            }
            #pragma unroll
            for (int ma = 0; ma < 2; ma++) {
                uint32_t lg = (uint32_t)((arow + ma * 16) * 64) + kb + akoff * 2;
                LDSM_X4(alf[ma][0], alf[ma][1], alf[ma][2], alf[ma][3],
                        st + TILEB + SWZ64(lg));
            }

            #pragma unroll
            for (int ma = 0; ma < 2; ma++)
                #pragma unroll
                for (int na = 0; na < 8; na++)
                    MMA_BF16(acc[ma][na], ahf[ma], bfr[na]);
            #pragma unroll
            for (int ma = 0; ma < 2; ma++)
                #pragma unroll
                for (int na = 0; na < 8; na++)
                    MMA_BF16(acc[ma][na], alf[ma], bfr[na]);

            #pragma unroll
            for (int j = 0; j < 4; j++) {
                uint32_t lg = (uint32_t)((brow + j * 16) * 64) + kb + bkoff * 2;
                LDSM_X4(bfr[2 * j][0], bfr[2 * j][1],
                        bfr[2 * j + 1][0], bfr[2 * j + 1][1],
                        st + 3u * TILEB + SWZ64(lg));
            }
            #pragma unroll
            for (int ma = 0; ma < 2; ma++)
                #pragma unroll
                for (int na = 0; na < 8; na++)
                    MMA_BF16(acc[ma][na], ahf[ma], bfr[na]);
        }
    }
#undef G_ISSUE

    #pragma unroll
    for (int na = 0; na < 8; na++) {
        const int cc = col0 + warp_n + na * 8 + (lane & 3) * 2;
        float2 bb = *(const float2*)(bias + cc);
        #pragma unroll
        for (int ma = 0; ma < 2; ma++) {
            const int r0r = row0 + warp_m + ma * 16 + (lane >> 2);
            float2 v0 = {acc[ma][na][0] + bb.x, acc[ma][na][1] + bb.y};
            float2 v1 = {acc[ma][na][2] + bb.x, acc[ma][na][3] + bb.y};
            *(float2*)(C + (size_t)r0r * Nn + cc) = v0;
            *(float2*)(C + (size_t)(r0r + 8) * Nn + cc) = v1;
        }
    }
}

// ---------------------------------------------------------------------------
// RMSNorm q,k + split to bf16 hi/lo, head-major [B,H,N,64].
// ---------------------------------------------------------------------------
__global__ void rmsnorm_split_kernel(const float* __restrict__ q_scale,
                                     const float* __restrict__ k_scale) {
    const int rr = blockIdx.x;
    const int h  = blockIdx.y * 4 + threadIdx.y;
    const int t  = threadIdx.x;
    const int b  = rr >> 10, n = rr & 1023;
    const float* in = g_qkv + (size_t)rr * K3_ + h * HD_;
    const size_t ob = ((size_t)(b * H_ + h) * N_ + n) * HD_;

    #pragma unroll
    for (int part = 0; part < 2; part++) {
        const float* ip = in + part * C_;
        float v0 = ip[t], v1 = ip[t + 32];
        float ss = v0 * v0 + v1 * v1;
        #pragma unroll
        for (int off = 16; off >= 1; off >>= 1)
            ss += __shfl_xor_sync(0xffffffffu, ss, off);
        float inv = 1.0f / (sqrtf(ss * (1.0f / 64.0f)) + 1e-8f);
        const float* sc = part ? k_scale : q_scale;
        float w0 = sc[t] * v0 * inv;
        float w1 = sc[t + 32] * v1 * inv;
        __nv_bfloat16 h0 = __float2bfloat16(w0);
        __nv_bfloat16 l0 = __float2bfloat16(w0 - __bfloat162float(h0));
        __nv_bfloat16 h1 = __float2bfloat16(w1);
        __nv_bfloat16 l1 = __float2bfloat16(w1 - __bfloat162float(h1));
        if (part == 0) {
            g_qh[ob + t] = h0;  g_ql[ob + t] = l0;
            g_qh[ob + t + 32] = h1;  g_ql[ob + t + 32] = l1;
        } else {
            g_kh[ob + t] = h0;  g_kl[ob + t] = l0;
            g_kh[ob + t + 32] = h1;  g_kl[ob + t + 32] = l1;
        }
    }
}

// ---------------------------------------------------------------------------
// V transpose + split: per head V[n][d] -> Vt[d][n] bf16 hi/lo.
// ---------------------------------------------------------------------------
__global__ void vt_split_kernel() {
    __shared__ float tile[32][33];
    const int tx = threadIdx.x, ty = threadIdx.y;
    const int n0 = blockIdx.x * 32;
    const int h  = blockIdx.y >> 1;
    const int d0 = (blockIdx.y & 1) * 32;
    const int b  = blockIdx.z;
    #pragma unroll
    for (int j = 0; j < 4; j++) {
        int n = n0 + ty + j * 8;
        tile[ty + j * 8][tx] =
            g_qkv[(size_t)(b * N_ + n) * K3_ + 2 * C_ + h * HD_ + d0 + tx];
    }
    __syncthreads();
    #pragma unroll
    for (int j = 0; j < 4; j++) {
        int d = d0 + ty + j * 8;
        float v = tile[tx][ty + j * 8];
        __nv_bfloat16 hh = __float2bfloat16(v);
        __nv_bfloat16 ll = __float2bfloat16(v - __bfloat162float(hh));
        size_t oi = ((size_t)(b * H_ + h) * HD_ + d) * N_ + n0 + tx;
        g_vth[oi] = hh;
        g_vtl[oi] = ll;
    }
}

// ---------------------------------------------------------------------------
// Tensor-core flash attention, k-tile width 64, 2 CTAs/SM.
// Per-warp state halved (sacc 32, p 32) so regs fit (256,2) without spills.
// smem per CTA:
//   K hi [64 x 72 bf16]  @ 0      (9216)    K lo @ 9216
//   Vt hi [64 x 72 bf16] @ 18432  (9216)    Vt lo @ 27648
//   bias [128 x 68 f32]  @ 36864 + s*34816  (Q hi/lo staged in bufs 0/1)
// Total 106496 B -> 2 CTAs/SM.
// ---------------------------------------------------------------------------
#define QKP      72
#define KTILE    9216u
#define KH_OFF   0u
#define KL_OFF   9216u
#define VH_OFF   18432u
#define VL_OFF   27648u
#define BIA_OFF  36864u
#define BIASZ    34816u              // 128 * 272
#define ATT_SMEM 106496

__global__ __launch_bounds__(256, 2) void mma_attn_kernel(
        const float* __restrict__ bias) {
    extern __shared__ char smem[];
    const uint32_t sb = smem_u32(smem);
    const int tid = threadIdx.x;
    const int lane = tid & 31;
    const int w = tid >> 5;
    const int q0 = blockIdx.x * 128;
    const int h  = blockIdx.y;
    const int b  = blockIdx.z;

    const size_t headNK = ((size_t)(b * H_ + h)) * N_ * HD_;
    const __nv_bfloat16* qh = g_qh + headNK + (size_t)q0 * HD_;
    const __nv_bfloat16* ql = g_ql + headNK + (size_t)q0 * HD_;
    const __nv_bfloat16* kh = g_kh + headNK;
    const __nv_bfloat16* kl = g_kl + headNK;
    const __nv_bfloat16* vth = g_vth + headNK;
    const __nv_bfloat16* vtl = g_vtl + headNK;
    const float* bptr = bias + (((size_t)(b * H_ + h)) * N_ + q0) * N_;

    // ---- Stage Q: hi -> bias buf0, lo -> bias buf1; fragments -> regs ----
    #pragma unroll
    for (int i = 0; i < 8; i++) {
        int u = tid + i * 256;
        int mat = u >> 10, r = (u >> 3) & 127, ch = u & 7;
        uint32_t sa = sb + BIA_OFF + mat * BIASZ + (r * QKP + ch * 8) * 2;
        const __nv_bfloat16* g = (mat ? ql : qh) + (size_t)r * HD_ + ch * 8;
        CP_ASYNC16(sa, g);
    }
    CP_COMMIT(); CP_WAIT0();
    __syncthreads();

    uint32_t qfh[4][4], qfl[4][4];
    {
        const int arow = w * 16 + (lane & 15);
        const int ak = (lane >> 4) * 8;
        #pragma unroll
        for (int ks = 0; ks < 4; ks++) {
            uint32_t ad = sb + BIA_OFF + (arow * QKP + ks * 16 + ak) * 2;
            LDSM_X4(qfh[ks][0], qfh[ks][1], qfh[ks][2], qfh[ks][3], ad);
            LDSM_X4(qfl[ks][0], qfl[ks][1], qfl[ks][2], qfl[ks][3], ad + BIASZ);
        }
    }
    __syncthreads();

#define ISSUE_KB(kt_) do {                                                    \
        const int k0_ = (kt_) * 64;                                           \
        _Pragma("unroll")                                                     \
        for (int i = 0; i < 4; i++) {                                         \
            int u = tid + i * 256;                                            \
            int mat = u >> 9, r = (u >> 3) & 63, ch = u & 7;                  \
            uint32_t sa = sb + mat * KTILE + (r * QKP + ch * 8) * 2;          \
            const __nv_bfloat16* g = (mat ? kl : kh) + (size_t)(k0_ + r) * HD_ + ch * 8; \
            CP_ASYNC16(sa, g);                                                \
        }                                                                     \
        const uint32_t bb_ = sb + BIA_OFF + ((kt_) & 1) * BIASZ;              \
        _Pragma("unroll")                                                     \
        for (int i = 0; i < 8; i++) {                                         \
            int u = tid + i * 256;                                            \
            int r = u >> 4, ch = u & 15;                                      \
            CP_ASYNC16(bb_ + r * 272u + ch * 16,                              \
                       bptr + (size_t)r * N_ + k0_ + ch * 4);                 \
        }                                                                     \
        CP_COMMIT();                                                          \
    } while (0)

#define ISSUE_V(kt_) do {                                                     \
        const int k0_ = (kt_) * 64;                                           \
        _Pragma("unroll")                                                     \
        for (int i = 0; i < 4; i++) {                                         \
            int u = tid + i * 256;                                            \
            int mat = u >> 9, d = (u >> 3) & 63, ch = u & 7;                  \
            uint32_t sa = sb + VH_OFF + mat * KTILE + (d * QKP + ch * 8) * 2; \
            const __nv_bfloat16* g = (mat ? vtl : vth) + (size_t)d * N_ + k0_ + ch * 8; \
            CP_ASYNC16(sa, g);                                                \
        }                                                                     \
        CP_COMMIT();                                                          \
    } while (0)

    ISSUE_KB(0);
    ISSUE_V(0);

    float oacc[8][4];
    #pragma unroll
    for (int dj = 0; dj < 8; dj++)
        #pragma unroll
        for (int q = 0; q < 4; q++) oacc[dj][q] = 0.0f;
    float l0 = 0.0f, l1 = 0.0f;

    const int brow_k = ((lane >> 4) & 1) * 8 + (lane & 7);
    const int bkoff  = ((lane >> 3) & 1) * 8;
    const int r0 = w * 16 + (lane >> 2);
    const int cc2 = (lane & 3) * 2;

    for (int kt = 0; kt < 16; kt++) {
        CP_WAIT1();
        __syncthreads();

        // ---- S = Q K^T over 64 k-cols (3-split) ----
        float sacc[8][4];
        #pragma unroll
        for (int j = 0; j < 8; j++)
            #pragma unroll
            for (int q = 0; q < 4; q++) sacc[j][q] = 0.0f;

        #pragma unroll
        for (int ks = 0; ks < 4; ks++) {
            uint32_t bf[8][2];
            #pragma unroll
            for (int j2 = 0; j2 < 4; j2++) {
                uint32_t bd = sb + KH_OFF +
                    ((j2 * 16 + brow_k) * QKP + ks * 16 + bkoff) * 2;
                LDSM_X4(bf[2 * j2][0], bf[2 * j2][1],
                        bf[2 * j2 + 1][0], bf[2 * j2 + 1][1], bd);
            }
            #pragma unroll
            for (int j = 0; j < 8; j++) MMA_BF16(sacc[j], qfh[ks], bf[j]);
            #pragma unroll
            for (int j = 0; j < 8; j++) MMA_BF16(sacc[j], qfl[ks], bf[j]);
        }
        #pragma unroll
        for (int ks = 0; ks < 4; ks++) {
            uint32_t bf[8][2];
            #pragma unroll
            for (int j2 = 0; j2 < 4; j2++) {
                uint32_t bd = sb + KL_OFF +
                    ((j2 * 16 + brow_k) * QKP + ks * 16 + bkoff) * 2;
                LDSM_X4(bf[2 * j2][0], bf[2 * j2][1],
                        bf[2 * j2 + 1][0], bf[2 * j2 + 1][1], bd);
            }
            #pragma unroll
            for (int j = 0; j < 8; j++) MMA_BF16(sacc[j], qfh[ks], bf[j]);
        }

        __syncthreads();
        if (kt + 1 < 16) ISSUE_KB(kt + 1);

        // ---- p = exp(s*scale + bias), no max shift ----
        const char* bcur = smem + BIA_OFF + (kt & 1) * BIASZ;
        #pragma unroll
        for (int j = 0; j < 8; j++) {
            const int col = j * 8 + cc2;
            float2 b0 = *(const float2*)(bcur + r0 * 272 + col * 4);
            float2 b1 = *(const float2*)(bcur + (r0 + 8) * 272 + col * 4);
            sacc[j][0] = fmaf(sacc[j][0], 0.125f, b0.x);
            sacc[j][1] = fmaf(sacc[j][1], 0.125f, b0.y);
            sacc[j][2] = fmaf(sacc[j][2], 0.125f, b1.x);
            sacc[j][3] = fmaf(sacc[j][3], 0.125f, b1.y);
        }

        float rs0 = 0.0f, rs1 = 0.0f;
        uint32_t pah[4][4], pal[4][4];
        #pragma unroll
        for (int ko = 0; ko < 4; ko++) {
            float p[8];
            #pragma unroll
            for (int half = 0; half < 2; half++) {
                const int j = 2 * ko + half;
                p[half * 4 + 0] = fexp(sacc[j][0]);
                p[half * 4 + 1] = fexp(sacc[j][1]);
                p[half * 4 + 2] = fexp(sacc[j][2]);
                p[half * 4 + 3] = fexp(sacc[j][3]);
                rs0 += p[half * 4 + 0] + p[half * 4 + 1];
                rs1 += p[half * 4 + 2] + p[half * 4 + 3];
            }
            #pragma unroll
            for (int half = 0; half < 2; half++) {
                uint32_t hi01 = pack_bf16(p[half * 4 + 1], p[half * 4 + 0]);
                uint32_t hi23 = pack_bf16(p[half * 4 + 3], p[half * 4 + 2]);
                float h0 = __int_as_float(hi01 << 16);
                float h1 = __int_as_float(hi01 & 0xffff0000u);
                float h2 = __int_as_float(hi23 << 16);
                float h3 = __int_as_float(hi23 & 0xffff0000u);
                pah[ko][half * 2 + 0] = hi01;
                pah[ko][half * 2 + 1] = hi23;
                pal[ko][half * 2 + 0] =
                    pack_bf16(p[half * 4 + 1] - h1, p[half * 4 + 0] - h0);
                pal[ko][half * 2 + 1] =
                    pack_bf16(p[half * 4 + 3] - h3, p[half * 4 + 2] - h2);
            }
        }

        rs0 += __shfl_xor_sync(0xffffffffu, rs0, 1);
        rs0 += __shfl_xor_sync(0xffffffffu, rs0, 2);
        rs1 += __shfl_xor_sync(0xffffffffu, rs1, 1);
        rs1 += __shfl_xor_sync(0xffffffffu, rs1, 2);
        l0 += rs0;
        l1 += rs1;

        CP_WAIT1();

        // ---- O += P V (3-split), ko 0..3 over 64 k ----
        #pragma unroll
        for (int ko = 0; ko < 4; ko++) {
            uint32_t vb[8][2];
            #pragma unroll
            for (int d2 = 0; d2 < 4; d2++) {
                uint32_t vd = sb + VH_OFF +
                    ((d2 * 16 + brow_k) * QKP + ko * 16 + bkoff) * 2;
                LDSM_X4(vb[2 * d2][0], vb[2 * d2][1],
                        vb[2 * d2 + 1][0], vb[2 * d2 + 1][1], vd);
            }
            #pragma unroll
            for (int dj = 0; dj < 8; dj++) MMA_BF16(oacc[dj], pah[ko], vb[dj]);
            #pragma unroll
            for (int dj = 0; dj < 8; dj++) MMA_BF16(oacc[dj], pal[ko], vb[dj]);
            #pragma unroll
            for (int d2 = 0; d2 < 4; d2++) {
                uint32_t vd = sb + VL_OFF +
                    ((d2 * 16 + brow_k) * QKP + ko * 16 + bkoff) * 2;
                LDSM_X4(vb[2 * d2][0], vb[2 * d2][1],
                        vb[2 * d2 + 1][0], vb[2 * d2 + 1][1], vd);
            }
            #pragma unroll
            for (int dj = 0; dj < 8; dj++) MMA_BF16(oacc[dj], pah[ko], vb[dj]);
        }

        __syncthreads();
        if (kt + 1 < 16) ISSUE_V(kt + 1);
    }

    const float il0 = 1.0f / l0, il1 = 1.0f / l1;
    #pragma unroll
    for (int dj = 0; dj < 8; dj++) {
        const int col = h * HD_ + dj * 8 + cc2;
        const size_t ra = (size_t)(b * N_ + q0 + r0) * C_ + col;
        const size_t rb = (size_t)(b * N_ + q0 + r0 + 8) * C_ + col;
        float v0 = oacc[dj][0] * il0, v1 = oacc[dj][1] * il0;
        float v2 = oacc[dj][2] * il1, v3 = oacc[dj][3] * il1;

        uint32_t h01 = pack_bf16(v1, v0);
        uint32_t h23 = pack_bf16(v3, v2);
        float f0 = __int_as_float(h01 << 16);
        float f1 = __int_as_float(h01 & 0xffff0000u);
        float f2 = __int_as_float(h23 << 16);
        float f3 = __int_as_float(h23 & 0xffff0000u);
        uint32_t l01 = pack_bf16(v1 - f1, v0 - f0);
        uint32_t l23 = pack_bf16(v3 - f3, v2 - f2);

        *(uint32_t*)(g_ah + ra) = h01;
        *(uint32_t*)(g_al + ra) = l01;
        *(uint32_t*)(g_ah + rb) = h23;
        *(uint32_t*)(g_al + rb) = l23;
    }
#undef ISSUE_KB
#undef ISSUE_V
}

// ---------------------------------------------------------------------------
// Launch
// ---------------------------------------------------------------------------
extern "C" void kernel_launch(void* const* d_in, const int* in_sizes, int n_in,
                              void* d_out, int out_size) {
    const float* x       = (const float*)d_in[0];
    const float* bias    = (const float*)d_in[1];
    const float* W_qkv   = (const float*)d_in[2];
    const float* b_qkv   = (const float*)d_in[3];
    const float* q_scale = (const float*)d_in[4];
    const float* k_scale = (const float*)d_in[5];
    const float* W_proj  = (const float*)d_in[6];
    const float* b_proj  = (const float*)d_in[7];
    float* out = (float*)d_out;

    float* qkv;
    __nv_bfloat16 *ah, *al, *wqh, *wql, *wph, *wpl;
    cudaGetSymbolAddress((void**)&qkv, g_qkv);
    cudaGetSymbolAddress((void**)&ah, g_ah);
    cudaGetSymbolAddress((void**)&al, g_al);
    cudaGetSymbolAddress((void**)&wqh, g_wqh);
    cudaGetSymbolAddress((void**)&wql, g_wql);
    cudaGetSymbolAddress((void**)&wph, g_wph);
    cudaGetSymbolAddress((void**)&wpl, g_wpl);

    cudaFuncSetAttribute(mma_gemm_kernel,
                         cudaFuncAttributeMaxDynamicSharedMemorySize, GSMEM);
    cudaFuncSetAttribute(mma_attn_kernel,
                         cudaFuncAttributeMaxDynamicSharedMemorySize, ATT_SMEM);

    // 0) Conversions
    split_kernel<<<(M_ * C_ / 4 + 255) / 256, 256>>>(x, ah, al, M_ * C_);
    transpose_split_kernel<<<dim3(K3_ / 32, C_ / 32), dim3(32, 8)>>>(W_qkv, wqh, wql, C_, K3_);
    transpose_split_kernel<<<dim3(C_ / 32, C_ / 32), dim3(32, 8)>>>(W_proj, wph, wpl, C_, C_);

    // 1) QKV GEMM
    mma_gemm_kernel<<<dim3(K3_ / 128, M_ / 128), 256, GSMEM>>>(
        ah, al, wqh, wql, b_qkv, qkv, M_, K3_, C_);

    // 2) RMSNorm + split q,k; transpose + split v
    rmsnorm_split_kernel<<<dim3(M_, 4), dim3(32, 4)>>>(q_scale, k_scale);
    vt_split_kernel<<<dim3(32, 32, 4), dim3(32, 8)>>>();

    // 3) Tensor-core flash attention (writes bf16 hi/lo directly)
    mma_attn_kernel<<<dim3(8, 16, 4), 256, ATT_SMEM>>>(bias);

    // 4) Proj GEMM (reads attention output hi/lo)
    mma_gemm_kernel<<<dim3(C_ / 128, M_ / 128), 256, GSMEM>>>(
        ah, al, wph, wpl, b_proj, out, M_, C_, C_);
}